// round 2
// baseline (speedup 1.0000x reference)
#include <cuda_runtime.h>
#include <math.h>

#define NQ      2048
#define ND      100000
#define DIM     16
#define THREADS 128
#define QPT     4
#define QBLK    (THREADS * QPT)   // 512 queries per block
#define QG      (NQ / QBLK)       // 4 query groups
#define TJ      128               // data points per smem tile
#define CHUNK   1408              // 11 tiles per chunk
#define CH      74                // 4*74 = 296 blocks = exactly 2 per SM
#define NPAD    (CH * CHUNK)      // 104192
#define PREP_BLOCKS  148
#define PREP_THREADS 256

// Scratch (no allocations allowed -> __device__ globals)
__device__ float g_coeff[NPAD];          // w_j * exp(-0.5*||d_j||^2), zero-padded
__device__ float g_partials[CH * NQ];    // per-chunk partial sums
__device__ float g_wpart[PREP_BLOCKS];   // per-block partial sums of w

// ---- packed f32x2 helpers (Blackwell FFMA2 path) ---------------------------
__device__ __forceinline__ unsigned long long pack2(float lo, float hi) {
    unsigned long long r;
    asm("mov.b64 %0, {%1, %2};" : "=l"(r) : "f"(lo), "f"(hi));
    return r;
}
__device__ __forceinline__ void unpack2(unsigned long long p, float& lo, float& hi) {
    asm("mov.b64 {%0, %1}, %2;" : "=f"(lo), "=f"(hi) : "l"(p));
}
__device__ __forceinline__ unsigned long long fma2(unsigned long long a,
                                                   unsigned long long b,
                                                   unsigned long long c) {
    unsigned long long r;
    asm("fma.rn.f32x2 %0, %1, %2, %3;" : "=l"(r) : "l"(a), "l"(b), "l"(c));
    return r;
}
__device__ __forceinline__ unsigned long long mul2(unsigned long long a,
                                                   unsigned long long b) {
    unsigned long long r;
    asm("mul.rn.f32x2 %0, %1, %2;" : "=l"(r) : "l"(a), "l"(b));
    return r;
}
__device__ __forceinline__ float ex2f(float x) {
    float r;
    asm("ex2.approx.f32 %0, %1;" : "=f"(r) : "f"(x));
    return r;
}

// ---------------------------------------------------------------------------
// Kernel 1: coeff_j = w_j * exp(-0.5 * ||d_j||^2); also block-partial sum of w
// ---------------------------------------------------------------------------
__global__ void kde_prep_kernel(const float* __restrict__ data,
                                const float* __restrict__ w) {
    int t = threadIdx.x;
    int bid = blockIdx.x;
    float wsum = 0.0f;
    for (int j = bid * PREP_THREADS + t; j < NPAD; j += PREP_BLOCKS * PREP_THREADS) {
        if (j < ND) {
            const float4* row = (const float4*)(data + (size_t)j * DIM);
            float dn = 0.0f;
#pragma unroll
            for (int v = 0; v < 4; v++) {
                float4 p = row[v];
                dn += p.x * p.x + p.y * p.y + p.z * p.z + p.w * p.w;
            }
            float wj = w[j];
            g_coeff[j] = wj * __expf(-0.5f * dn);
            wsum += wj;
        } else {
            g_coeff[j] = 0.0f;
        }
    }
    __shared__ float red[PREP_THREADS];
    red[t] = wsum;
    __syncthreads();
#pragma unroll
    for (int s = PREP_THREADS / 2; s > 0; s >>= 1) {
        if (t < s) red[t] += red[t + s];
        __syncthreads();
    }
    if (t == 0) g_wpart[bid] = red[0];
}

// ---------------------------------------------------------------------------
// Kernel 2: main pairwise loop, packed f32x2 dot products.
//   Block (qg, ch): 512 queries (4/thread, packed as two f32x2 chains),
//   streams its 1408-point chunk through a 128-point DUPLICATED smem tile:
//   each data value stored as a (v,v) 64-bit pair so LDS.128 yields
//   ready-packed FFMA2 operands (no per-element pack MOVs).
// ---------------------------------------------------------------------------
__global__ __launch_bounds__(THREADS)
void kde_main_kernel(const float* __restrict__ X,
                     const float* __restrict__ data) {
    int t  = threadIdx.x;
    int qg = blockIdx.x;
    int ch = blockIdx.y;

    __shared__ ulonglong2 sd[TJ * 8];  // 128 pts x 16 vals, each duplicated (v,v); 16 KB
    __shared__ float      sc[TJ];      // coeffs

    // Load 4 queries, pack as (q0,q1) and (q2,q3) pairs per dim
    unsigned long long xq01[DIM], xq23[DIM];
    {
        int q0 = qg * QBLK + 0 * THREADS + t;
        int q1 = qg * QBLK + 1 * THREADS + t;
        int q2 = qg * QBLK + 2 * THREADS + t;
        int q3 = qg * QBLK + 3 * THREADS + t;
        const float* r0 = X + (size_t)q0 * DIM;
        const float* r1 = X + (size_t)q1 * DIM;
        const float* r2 = X + (size_t)q2 * DIM;
        const float* r3 = X + (size_t)q3 * DIM;
#pragma unroll
        for (int k = 0; k < DIM; k++) {
            xq01[k] = pack2(r0[k], r1[k]);
            xq23[k] = pack2(r2[k], r3[k]);
        }
    }

    const unsigned long long LOG2E2 =
        pack2(1.4426950408889634f, 1.4426950408889634f);
    const unsigned long long ZERO2 = pack2(0.0f, 0.0f);

    float acc[QPT] = {0.0f, 0.0f, 0.0f, 0.0f};
    int j0 = ch * CHUNK;

    for (int tile = 0; tile < CHUNK; tile += TJ) {
        int base = j0 + tile;
        __syncthreads();  // protect previous tile's reads
        // Stage 128 points duplicated: element i covers point (i>>3),
        // float-pair (i&7). Consecutive threads -> consecutive 16B stores.
#pragma unroll
        for (int i = t; i < TJ * 8; i += THREADS) {
            int jj = base + (i >> 3);
            float2 v = make_float2(0.0f, 0.0f);
            if (jj < ND) v = ((const float2*)data)[(size_t)jj * 8 + (i & 7)];
            ulonglong2 o;
            o.x = pack2(v.x, v.x);
            o.y = pack2(v.y, v.y);
            sd[i] = o;
        }
        sc[t] = g_coeff[base + t];  // TJ == THREADS, padded array covers OOB
        __syncthreads();

#pragma unroll 4
        for (int jj = 0; jj < TJ; jj++) {
            unsigned long long dot01 = ZERO2, dot23 = ZERO2;
#pragma unroll
            for (int i = 0; i < 8; i++) {
                ulonglong2 pp = sd[jj * 8 + i];  // broadcast LDS.128
                dot01 = fma2(pp.x, xq01[2 * i + 0], dot01);
                dot23 = fma2(pp.x, xq23[2 * i + 0], dot23);
                dot01 = fma2(pp.y, xq01[2 * i + 1], dot01);
                dot23 = fma2(pp.y, xq23[2 * i + 1], dot23);
            }
            float c = sc[jj];
            unsigned long long m01 = mul2(dot01, LOG2E2);
            unsigned long long m23 = mul2(dot23, LOG2E2);
            float m0, m1, m2, m3;
            unpack2(m01, m0, m1);
            unpack2(m23, m2, m3);
            acc[0] = fmaf(c, ex2f(m0), acc[0]);
            acc[1] = fmaf(c, ex2f(m1), acc[1]);
            acc[2] = fmaf(c, ex2f(m2), acc[2]);
            acc[3] = fmaf(c, ex2f(m3), acc[3]);
        }
    }

#pragma unroll
    for (int k = 0; k < QPT; k++) {
        int q = qg * QBLK + k * THREADS + t;
        g_partials[(size_t)ch * NQ + q] = acc[k];
    }
}

// ---------------------------------------------------------------------------
// Kernel 3: finalize.
//   log_density[q] = log(S_q) - 0.5*||x_q||^2 - (d/2)*log(2*pi) - log(sum w)
//   All reductions in fixed order -> deterministic.
// ---------------------------------------------------------------------------
__global__ void kde_final_kernel(const float* __restrict__ X,
                                 float* __restrict__ out) {
    int q = blockIdx.x * blockDim.x + threadIdx.x;
    if (q >= NQ) return;

    float qn = 0.0f;
    const float4* row = (const float4*)(X + (size_t)q * DIM);
#pragma unroll
    for (int v = 0; v < 4; v++) {
        float4 p = row[v];
        qn += p.x * p.x + p.y * p.y + p.z * p.z + p.w * p.w;
    }

    float S = 0.0f;
#pragma unroll 8
    for (int ch = 0; ch < CH; ch++) S += g_partials[(size_t)ch * NQ + q];

    float sumw = 0.0f;
#pragma unroll 4
    for (int b = 0; b < PREP_BLOCKS; b++) sumw += g_wpart[b];

    const float LOG2PI = 1.8378770664093453f;
    out[q] = logf(S) - 0.5f * qn - 8.0f * LOG2PI - logf(sumw);
}

// ---------------------------------------------------------------------------
extern "C" void kernel_launch(void* const* d_in, const int* in_sizes, int n_in,
                              void* d_out, int out_size) {
    const float* X    = (const float*)d_in[0];  // [2048, 16]
    const float* data = (const float*)d_in[1];  // [100000, 16]
    const float* w    = (const float*)d_in[2];  // [100000]
    float* out = (float*)d_out;                 // [2048]

    kde_prep_kernel<<<PREP_BLOCKS, PREP_THREADS>>>(data, w);
    kde_main_kernel<<<dim3(QG, CH), THREADS>>>(X, data);
    kde_final_kernel<<<(NQ + 255) / 256, 256>>>(X, out);
}

// round 4
// speedup vs baseline: 2.3724x; 2.3724x over previous
#include <cuda_runtime.h>
#include <cuda_bf16.h>
#include <math.h>
#include <stdint.h>

#define NQ       2048
#define ND       100000
#define DIM      16
#define QTILES   16            // 2048 / 128 queries per CTA
#define DS       37            // data splits; 16*37 = 592 CTAs = 4/SM
#define TILE     128           // data points per smem tile
#define NT       22            // tiles per split
#define PTS_PER_SPLIT (TILE * NT)            // 2816
#define NPAD     (DS * PTS_PER_SPLIT)        // 104192
#define KC       48            // K = [h,h,l] x 16
#define ROWPAD   72            // smem row stride in bf16 elems (conflict-free)
#define THREADS  256
#define PREP_BLOCKS  148
#define PREP_THREADS 256

// ---- device scratch (no allocations allowed) ----
__device__ __nv_bfloat16 g_dcat[(size_t)NPAD * KC];  // [dh, dl, dh] per point
__device__ __nv_bfloat16 g_xcat[(size_t)NQ * KC];    // [yh, yh, yl], y = x*log2e
__device__ float g_coeff[NPAD];                      // w_j * exp(-0.5*||d||^2)
__device__ float g_partials[DS * NQ];
__device__ float g_wpart[PREP_BLOCKS];

// ---- helpers ----
__device__ __forceinline__ uint32_t s2u(const void* p) {
    uint32_t a;
    asm("{ .reg .u64 t; cvta.to.shared.u64 t, %1; cvt.u32.u64 %0, t; }"
        : "=r"(a) : "l"(p));
    return a;
}
__device__ __forceinline__ void cpa16(uint32_t dst, const void* src) {
    asm volatile("cp.async.cg.shared.global [%0], [%1], 16;"
                 :: "r"(dst), "l"(src));
}
#define CP_COMMIT() asm volatile("cp.async.commit_group;" ::: "memory")
#define CP_WAIT0()  asm volatile("cp.async.wait_group 0;" ::: "memory")
#define CP_WAIT1()  asm volatile("cp.async.wait_group 1;" ::: "memory")

__device__ __forceinline__ float ex2f(float x) {
    float r; asm("ex2.approx.f32 %0, %1;" : "=f"(r) : "f"(x)); return r;
}
__device__ __forceinline__ void mma16816(float* d, const uint32_t* a,
                                         uint32_t b0, uint32_t b1) {
    asm volatile(
        "mma.sync.aligned.m16n8k16.row.col.f32.bf16.bf16.f32 "
        "{%0,%1,%2,%3}, {%4,%5,%6,%7}, {%8,%9}, {%0,%1,%2,%3};"
        : "+f"(d[0]), "+f"(d[1]), "+f"(d[2]), "+f"(d[3])
        : "r"(a[0]), "r"(a[1]), "r"(a[2]), "r"(a[3]), "r"(b0), "r"(b1));
}

// ---------------------------------------------------------------------------
// Prep 1: data -> split bf16 [dh, dl, dh]; coeff = w*exp(-||d||^2/2); w-sums
// ---------------------------------------------------------------------------
__global__ void kde_prep_data(const float* __restrict__ data,
                              const float* __restrict__ w) {
    int t = threadIdx.x, bid = blockIdx.x;
    float wsum = 0.0f;
    for (int j = bid * PREP_THREADS + t; j < NPAD; j += PREP_BLOCKS * PREP_THREADS) {
        __nv_bfloat16 row[KC];
        float cj = 0.0f;
        if (j < ND) {
            const float4* src = (const float4*)(data + (size_t)j * DIM);
            float dn = 0.0f;
#pragma unroll
            for (int v = 0; v < 4; v++) {
                float4 p = src[v];
                dn += p.x * p.x + p.y * p.y + p.z * p.z + p.w * p.w;
                float e[4] = {p.x, p.y, p.z, p.w};
#pragma unroll
                for (int u = 0; u < 4; u++) {
                    int k = v * 4 + u;
                    __nv_bfloat16 h = __float2bfloat16_rn(e[u]);
                    __nv_bfloat16 l = __float2bfloat16_rn(e[u] - __bfloat162float(h));
                    row[k]      = h;   // pairs with yh
                    row[16 + k] = l;   // pairs with yh
                    row[32 + k] = h;   // pairs with yl
                }
            }
            float wj = w[j];
            cj = wj * __expf(-0.5f * dn);
            wsum += wj;
        } else {
#pragma unroll
            for (int k = 0; k < KC; k++) row[k] = __float2bfloat16_rn(0.0f);
        }
        g_coeff[j] = cj;
        uint4* dst = (uint4*)(g_dcat + (size_t)j * KC);
        const uint4* srcr = (const uint4*)row;
#pragma unroll
        for (int v = 0; v < 6; v++) dst[v] = srcr[v];
    }
    __shared__ float red[PREP_THREADS];
    red[t] = wsum;
    __syncthreads();
#pragma unroll
    for (int s = PREP_THREADS / 2; s > 0; s >>= 1) {
        if (t < s) red[t] += red[t + s];
        __syncthreads();
    }
    if (t == 0) g_wpart[bid] = red[0];
}

// ---------------------------------------------------------------------------
// Prep 2: queries -> y = x*log2e, split bf16 -> [yh, yh, yl]
// ---------------------------------------------------------------------------
__global__ void kde_prep_x(const float* __restrict__ X) {
    int q = blockIdx.x * blockDim.x + threadIdx.x;
    if (q >= NQ) return;
    const float LOG2E = 1.4426950408889634f;
    __nv_bfloat16 row[KC];
    const float4* src = (const float4*)(X + (size_t)q * DIM);
#pragma unroll
    for (int v = 0; v < 4; v++) {
        float4 p = src[v];
        float e[4] = {p.x, p.y, p.z, p.w};
#pragma unroll
        for (int u = 0; u < 4; u++) {
            int k = v * 4 + u;
            float y = e[u] * LOG2E;
            __nv_bfloat16 h = __float2bfloat16_rn(y);
            __nv_bfloat16 l = __float2bfloat16_rn(y - __bfloat162float(h));
            row[k]      = h;
            row[16 + k] = h;
            row[32 + k] = l;
        }
    }
    uint4* dst = (uint4*)(g_xcat + (size_t)q * KC);
    const uint4* srcr = (const uint4*)row;
#pragma unroll
    for (int v = 0; v < 6; v++) dst[v] = srcr[v];
}

// ---------------------------------------------------------------------------
// Main: CTA (qt, ds): 128 queries x 2816 points.
//   Warp w: 16 queries. mma.sync m16n8k16 bf16 dots (log2-domain),
//   epilogue ex2 + coeff FMA. Double-buffered cp.async tiles.
// ---------------------------------------------------------------------------
__global__ __launch_bounds__(THREADS, 4)
void kde_main_kernel() {
    __shared__ __nv_bfloat16 sd[2][TILE * ROWPAD];  // 2 x 18 KB
    __shared__ float sc[2][TILE];

    int tid = threadIdx.x;
    int w = tid >> 5, lane = tid & 31;
    int qt = blockIdx.x, ds = blockIdx.y;
    int p0base = ds * PTS_PER_SPLIT;

    // A fragments: 16 queries for this warp, 3 k-chunks, once per CTA life.
    int qb = qt * 128 + w * 16;
    int r = lane >> 2, c0 = (lane & 3) * 2;
    uint32_t afrag[3][4];
#pragma unroll
    for (int kc = 0; kc < 3; kc++) {
        const __nv_bfloat16* base = g_xcat + (size_t)(qb + r) * KC + kc * 16 + c0;
        afrag[kc][0] = *(const uint32_t*)(base);
        afrag[kc][1] = *(const uint32_t*)(base + 8 * KC);
        afrag[kc][2] = *(const uint32_t*)(base + 8);
        afrag[kc][3] = *(const uint32_t*)(base + 8 * KC + 8);
    }

    // Stage tile 0
    {
        const char* bsrc = (const char*)(g_dcat + (size_t)p0base * KC);
        uint32_t sbb = s2u(sd[0]);
#pragma unroll
        for (int i = tid; i < TILE * 6; i += THREADS) {
            int row = i / 6, c = i % 6;
            cpa16(sbb + row * (ROWPAD * 2) + c * 16, bsrc + row * 96 + c * 16);
        }
        if (tid < 32)
            cpa16(s2u(sc[0]) + tid * 16, (const char*)(g_coeff + p0base) + tid * 16);
        CP_COMMIT();
    }

    float acc0 = 0.0f, acc1 = 0.0f;
    int buf = 0;

    for (int it = 0; it < NT; ++it) {
        if (it + 1 < NT) {
            int p0 = p0base + (it + 1) * TILE;
            const char* bsrc = (const char*)(g_dcat + (size_t)p0 * KC);
            uint32_t sbb = s2u(sd[buf ^ 1]);
#pragma unroll
            for (int i = tid; i < TILE * 6; i += THREADS) {
                int row = i / 6, c = i % 6;
                cpa16(sbb + row * (ROWPAD * 2) + c * 16, bsrc + row * 96 + c * 16);
            }
            if (tid < 32)
                cpa16(s2u(sc[buf ^ 1]) + tid * 16, (const char*)(g_coeff + p0) + tid * 16);
            CP_COMMIT();
            CP_WAIT1();   // tile `it` resident
        } else {
            CP_WAIT0();
        }
        __syncthreads();

        const uint32_t* sdw = (const uint32_t*)sd[buf];
        const float* scf = sc[buf];
#pragma unroll 4
        for (int nc = 0; nc < 16; nc++) {
            float d[4] = {0.0f, 0.0f, 0.0f, 0.0f};
            int n = nc * 8 + (lane >> 2);
            int widx = n * (ROWPAD / 2) + (lane & 3);
#pragma unroll
            for (int kc = 0; kc < 3; kc++) {
                uint32_t b0 = sdw[widx + kc * 8];
                uint32_t b1 = sdw[widx + kc * 8 + 4];
                mma16816(d, afrag[kc], b0, b1);
            }
            float2 cj = *(const float2*)(scf + nc * 8 + c0);
            acc0 = fmaf(cj.x, ex2f(d[0]), acc0);
            acc0 = fmaf(cj.y, ex2f(d[1]), acc0);
            acc1 = fmaf(cj.x, ex2f(d[2]), acc1);
            acc1 = fmaf(cj.y, ex2f(d[3]), acc1);
        }
        __syncthreads();  // done reading buf before restage
        buf ^= 1;
    }

    // Quad reduction over the 4 column-lanes (deterministic fixed order)
    acc0 += __shfl_xor_sync(0xFFFFFFFFu, acc0, 1);
    acc0 += __shfl_xor_sync(0xFFFFFFFFu, acc0, 2);
    acc1 += __shfl_xor_sync(0xFFFFFFFFu, acc1, 1);
    acc1 += __shfl_xor_sync(0xFFFFFFFFu, acc1, 2);
    if ((lane & 3) == 0) {
        g_partials[(size_t)ds * NQ + qb + r]     = acc0;
        g_partials[(size_t)ds * NQ + qb + r + 8] = acc1;
    }
}

// ---------------------------------------------------------------------------
// Finalize: log(S) - 0.5||x||^2 - 8*log(2*pi) - log(sum w)
// ---------------------------------------------------------------------------
__global__ void kde_final_kernel(const float* __restrict__ X,
                                 float* __restrict__ out) {
    int q = blockIdx.x * blockDim.x + threadIdx.x;
    if (q >= NQ) return;

    float qn = 0.0f;
    const float4* row = (const float4*)(X + (size_t)q * DIM);
#pragma unroll
    for (int v = 0; v < 4; v++) {
        float4 p = row[v];
        qn += p.x * p.x + p.y * p.y + p.z * p.z + p.w * p.w;
    }
    float S = 0.0f;
#pragma unroll
    for (int i = 0; i < DS; i++) S += g_partials[(size_t)i * NQ + q];
    float sumw = 0.0f;
#pragma unroll 4
    for (int b = 0; b < PREP_BLOCKS; b++) sumw += g_wpart[b];

    const float LOG2PI = 1.8378770664093453f;
    out[q] = logf(S) - 0.5f * qn - 8.0f * LOG2PI - logf(sumw);
}

// ---------------------------------------------------------------------------
extern "C" void kernel_launch(void* const* d_in, const int* in_sizes, int n_in,
                              void* d_out, int out_size) {
    const float* X    = (const float*)d_in[0];  // [2048, 16]
    const float* data = (const float*)d_in[1];  // [100000, 16]
    const float* w    = (const float*)d_in[2];  // [100000]
    float* out = (float*)d_out;                 // [2048]

    kde_prep_data<<<PREP_BLOCKS, PREP_THREADS>>>(data, w);
    kde_prep_x<<<(NQ + 255) / 256, 256>>>(X);
    kde_main_kernel<<<dim3(QTILES, DS), THREADS>>>();
    kde_final_kernel<<<(NQ + 255) / 256, 256>>>(X, out);
}

// round 5
// speedup vs baseline: 2.6566x; 1.1198x over previous
#include <cuda_runtime.h>
#include <cuda_bf16.h>
#include <math.h>
#include <stdint.h>

#define NQ       2048
#define ND       100000
#define DIM      16
#define QTILES   16            // 2048 / 128 queries per CTA
#define DS       37            // data splits; 16*37 = 592 CTAs = 4/SM
#define TILE     128           // data points per smem tile
#define NT       22            // tiles per split
#define PTS_PER_SPLIT (TILE * NT)            // 2816
#define NPAD     (DS * PTS_PER_SPLIT)        // 104192
#define THREADS  256
#define PREP_BLOCKS  407       // NPAD / 256 exactly
#define PREP_THREADS 256

// ---- device scratch (no allocations allowed) ----
// g_dcat: per point, 16 u32 words, PERMUTED: pos 4g+{0,1,2,3} = words {g, g+4, 8+g, 12+g}
//         of the natural [dh(8 words), dl(8 words)] layout. One LDS.128 per lane
//         yields the full m16n8k16 B fragment pair for both dh and dl.
__device__ uint4 g_dcat[(size_t)NPAD * 4];
__device__ __nv_bfloat16 g_xcat[(size_t)NQ * 32];   // [yh(16), yl(16)], y = x*log2e
__device__ float g_coeff[NPAD];                     // w_j * exp(-0.5*||d||^2)
__device__ float g_partials[DS * 2 * NQ];
__device__ float g_wpart[PREP_BLOCKS];

// ---- helpers ----
__device__ __forceinline__ uint32_t s2u(const void* p) {
    uint32_t a;
    asm("{ .reg .u64 t; cvta.to.shared.u64 t, %1; cvt.u32.u64 %0, t; }"
        : "=r"(a) : "l"(p));
    return a;
}
__device__ __forceinline__ void cpa16(uint32_t dst, const void* src) {
    asm volatile("cp.async.cg.shared.global [%0], [%1], 16;"
                 :: "r"(dst), "l"(src));
}
#define CP_COMMIT() asm volatile("cp.async.commit_group;" ::: "memory")
#define CP_WAIT0()  asm volatile("cp.async.wait_group 0;" ::: "memory")
#define CP_WAIT1()  asm volatile("cp.async.wait_group 1;" ::: "memory")

__device__ __forceinline__ float ex2f(float x) {
    float r; asm("ex2.approx.f32 %0, %1;" : "=f"(r) : "f"(x)); return r;
}
__device__ __forceinline__ void mma16816(float* d, const uint32_t* a,
                                         uint32_t b0, uint32_t b1) {
    asm volatile(
        "mma.sync.aligned.m16n8k16.row.col.f32.bf16.bf16.f32 "
        "{%0,%1,%2,%3}, {%4,%5,%6,%7}, {%8,%9}, {%0,%1,%2,%3};"
        : "+f"(d[0]), "+f"(d[1]), "+f"(d[2]), "+f"(d[3])
        : "r"(a[0]), "r"(a[1]), "r"(a[2]), "r"(a[3]), "r"(b0), "r"(b1));
}
__device__ __forceinline__ uint32_t lds128(uint32_t addr, uint32_t* v) {
    asm volatile("ld.shared.v4.u32 {%0,%1,%2,%3}, [%4];"
                 : "=r"(v[0]), "=r"(v[1]), "=r"(v[2]), "=r"(v[3]) : "r"(addr));
    return addr;
}
__device__ __forceinline__ uint32_t packbf(float hi, float lo) {
    // returns (bf16(hi) | bf16(lo)<<16)? No: pack (lo elem, hi elem) as (e0,e1)
    __nv_bfloat162 t = __floats2bfloat162_rn(hi, lo);
    return *(uint32_t*)&t;
}

// ---------------------------------------------------------------------------
// Prep 1: one point per thread. bf16 hi/lo split, permuted word layout,
// coeff = w*exp(-||d||^2/2), block-partial sums of w.
// ---------------------------------------------------------------------------
__global__ __launch_bounds__(PREP_THREADS)
void kde_prep_data(const float* __restrict__ data,
                   const float* __restrict__ w) {
    int t = threadIdx.x;
    int j = blockIdx.x * PREP_THREADS + t;   // < NPAD always (grid exact)

    uint32_t wd[16];   // natural words: 0..7 = dh pairs, 8..15 = dl pairs
    float cj = 0.0f, wj = 0.0f;
    if (j < ND) {
        const float4* src = (const float4*)(data + (size_t)j * DIM);
        float dn = 0.0f;
#pragma unroll
        for (int v = 0; v < 4; v++) {
            float4 p = src[v];
            dn += p.x * p.x + p.y * p.y + p.z * p.z + p.w * p.w;
            float e[4] = {p.x, p.y, p.z, p.w};
#pragma unroll
            for (int u = 0; u < 2; u++) {
                float a = e[u * 2], b = e[u * 2 + 1];
                __nv_bfloat16 ha = __float2bfloat16_rn(a);
                __nv_bfloat16 hb = __float2bfloat16_rn(b);
                float la = a - __bfloat162float(ha);
                float lb = b - __bfloat162float(hb);
                uint32_t hw = ((uint32_t)*(uint16_t*)&hb << 16) | *(uint16_t*)&ha;
                __nv_bfloat16 hla = __float2bfloat16_rn(la);
                __nv_bfloat16 hlb = __float2bfloat16_rn(lb);
                uint32_t lw = ((uint32_t)*(uint16_t*)&hlb << 16) | *(uint16_t*)&hla;
                wd[v * 2 + u] = hw;
                wd[8 + v * 2 + u] = lw;
            }
        }
        wj = w[j];
        cj = wj * __expf(-0.5f * dn);
    } else {
#pragma unroll
        for (int k = 0; k < 16; k++) wd[k] = 0u;
    }
    g_coeff[j] = cj;
    // permuted store: pos 4g+{0..3} = wd[g], wd[g+4], wd[8+g], wd[12+g]
#pragma unroll
    for (int g = 0; g < 4; g++) {
        uint4 o;
        o.x = wd[g]; o.y = wd[g + 4]; o.z = wd[8 + g]; o.w = wd[12 + g];
        g_dcat[(size_t)j * 4 + g] = o;
    }

    __shared__ float red[PREP_THREADS];
    red[t] = wj;
    __syncthreads();
#pragma unroll
    for (int s = PREP_THREADS / 2; s > 0; s >>= 1) {
        if (t < s) red[t] += red[t + s];
        __syncthreads();
    }
    if (t == 0) g_wpart[blockIdx.x] = red[0];
}

// ---------------------------------------------------------------------------
// Prep 2: queries -> y = x*log2e, split bf16 -> [yh(16), yl(16)]
// ---------------------------------------------------------------------------
__global__ void kde_prep_x(const float* __restrict__ X) {
    int q = blockIdx.x * blockDim.x + threadIdx.x;
    if (q >= NQ) return;
    const float LOG2E = 1.4426950408889634f;
    __nv_bfloat16 row[32];
    const float4* src = (const float4*)(X + (size_t)q * DIM);
#pragma unroll
    for (int v = 0; v < 4; v++) {
        float4 p = src[v];
        float e[4] = {p.x, p.y, p.z, p.w};
#pragma unroll
        for (int u = 0; u < 4; u++) {
            int k = v * 4 + u;
            float y = e[u] * LOG2E;
            __nv_bfloat16 h = __float2bfloat16_rn(y);
            __nv_bfloat16 l = __float2bfloat16_rn(y - __bfloat162float(h));
            row[k]      = h;
            row[16 + k] = l;
        }
    }
    uint4* dst = (uint4*)(g_xcat + (size_t)q * 32);
    const uint4* srcr = (const uint4*)row;
#pragma unroll
    for (int v = 0; v < 4; v++) dst[v] = srcr[v];
}

// ---------------------------------------------------------------------------
// Main: CTA (qt, ds): 128 queries x 2816 points.
//   Warp w: wm = w>>1 (32 queries = 2 m-tiles), wn = w&1 (64 points).
//   Per 8-pt n-tile: 1 LDS.128 -> {dh_b0, dh_b1, dl_b0, dl_b1};
//   3 MMAs per m-tile (yh*dh, yl*dh, yh*dl), ex2 + coeff FMA epilogue.
// ---------------------------------------------------------------------------
__global__ __launch_bounds__(THREADS, 4)
void kde_main_kernel() {
    __shared__ uint4 sd[2][TILE * 4];   // 2 x 8 KB, 64B per point (permuted)
    __shared__ float sc[2][TILE];

    int tid = threadIdx.x;
    int w = tid >> 5, lane = tid & 31;
    int wm = w >> 1, wn = w & 1;
    int qt = blockIdx.x, ds = blockIdx.y;
    int p0base = ds * PTS_PER_SPLIT;
    int r = lane >> 2, c2 = (lane & 3) * 2;

    // A fragments: 32 queries (2 m-tiles), yh + yl
    int qb = qt * 128 + wm * 32;
    uint32_t afrag[2][2][4];
#pragma unroll
    for (int mt = 0; mt < 2; mt++)
#pragma unroll
        for (int tt = 0; tt < 2; tt++) {
            const __nv_bfloat16* base =
                g_xcat + (size_t)(qb + mt * 16 + r) * 32 + tt * 16 + c2;
            afrag[mt][tt][0] = *(const uint32_t*)(base);
            afrag[mt][tt][1] = *(const uint32_t*)(base + 8 * 32);
            afrag[mt][tt][2] = *(const uint32_t*)(base + 8);
            afrag[mt][tt][3] = *(const uint32_t*)(base + 8 * 32 + 8);
        }

    // Stage tile 0
    {
        const char* bsrc = (const char*)(g_dcat + (size_t)p0base * 4);
        uint32_t sbb = s2u(sd[0]);
#pragma unroll
        for (int i = tid; i < TILE * 4; i += THREADS)
            cpa16(sbb + i * 16, bsrc + i * 16);
        if (tid < 32)
            cpa16(s2u(sc[0]) + tid * 16, (const char*)(g_coeff + p0base) + tid * 16);
        CP_COMMIT();
    }

    float acc[2][2] = {{0.0f, 0.0f}, {0.0f, 0.0f}};
    int buf = 0;

    for (int it = 0; it < NT; ++it) {
        if (it + 1 < NT) {
            int p0 = p0base + (it + 1) * TILE;
            const char* bsrc = (const char*)(g_dcat + (size_t)p0 * 4);
            uint32_t sbb = s2u(sd[buf ^ 1]);
#pragma unroll
            for (int i = tid; i < TILE * 4; i += THREADS)
                cpa16(sbb + i * 16, bsrc + i * 16);
            if (tid < 32)
                cpa16(s2u(sc[buf ^ 1]) + tid * 16, (const char*)(g_coeff + p0) + tid * 16);
            CP_COMMIT();
            CP_WAIT1();   // tile `it` resident
        } else {
            CP_WAIT0();
        }
        __syncthreads();

        uint32_t sdb = s2u(sd[buf]);
        const float* scf = sc[buf];
#pragma unroll
        for (int nt = 0; nt < 8; nt++) {
            int n0 = wn * 64 + nt * 8;
            uint32_t b[4];
            lds128(sdb + (uint32_t)(n0 + r) * 64 + (uint32_t)(lane & 3) * 16, b);
            float d0[4] = {0, 0, 0, 0}, d1[4] = {0, 0, 0, 0};
            // b[0],b[1] = dh fragment; b[2],b[3] = dl fragment
            mma16816(d0, afrag[0][0], b[0], b[1]);   // yh * dh
            mma16816(d1, afrag[1][0], b[0], b[1]);
            mma16816(d0, afrag[0][1], b[0], b[1]);   // yl * dh
            mma16816(d1, afrag[1][1], b[0], b[1]);
            mma16816(d0, afrag[0][0], b[2], b[3]);   // yh * dl
            mma16816(d1, afrag[1][0], b[2], b[3]);

            float2 cj = *(const float2*)(scf + n0 + c2);
            acc[0][0] = fmaf(cj.x, ex2f(d0[0]), acc[0][0]);
            acc[0][0] = fmaf(cj.y, ex2f(d0[1]), acc[0][0]);
            acc[0][1] = fmaf(cj.x, ex2f(d0[2]), acc[0][1]);
            acc[0][1] = fmaf(cj.y, ex2f(d0[3]), acc[0][1]);
            acc[1][0] = fmaf(cj.x, ex2f(d1[0]), acc[1][0]);
            acc[1][0] = fmaf(cj.y, ex2f(d1[1]), acc[1][0]);
            acc[1][1] = fmaf(cj.x, ex2f(d1[2]), acc[1][1]);
            acc[1][1] = fmaf(cj.y, ex2f(d1[3]), acc[1][1]);
        }
        __syncthreads();  // done reading buf before restage
        buf ^= 1;
    }

    // Reduce over the 4 column-lanes (fixed order, deterministic)
#pragma unroll
    for (int mt = 0; mt < 2; mt++)
#pragma unroll
        for (int hh = 0; hh < 2; hh++) {
            float v = acc[mt][hh];
            v += __shfl_xor_sync(0xFFFFFFFFu, v, 1);
            v += __shfl_xor_sync(0xFFFFFFFFu, v, 2);
            acc[mt][hh] = v;
        }
    if ((lane & 3) == 0) {
        size_t base = (size_t)(ds * 2 + wn) * NQ + qb;
        g_partials[base + 0 * 16 + r]     = acc[0][0];
        g_partials[base + 0 * 16 + r + 8] = acc[0][1];
        g_partials[base + 1 * 16 + r]     = acc[1][0];
        g_partials[base + 1 * 16 + r + 8] = acc[1][1];
    }
}

// ---------------------------------------------------------------------------
// Finalize: log(S) - 0.5||x||^2 - 8*log(2*pi) - log(sum w)
// ---------------------------------------------------------------------------
__global__ void kde_final_kernel(const float* __restrict__ X,
                                 float* __restrict__ out) {
    int q = blockIdx.x * blockDim.x + threadIdx.x;
    if (q >= NQ) return;

    float qn = 0.0f;
    const float4* row = (const float4*)(X + (size_t)q * DIM);
#pragma unroll
    for (int v = 0; v < 4; v++) {
        float4 p = row[v];
        qn += p.x * p.x + p.y * p.y + p.z * p.z + p.w * p.w;
    }
    float S = 0.0f;
#pragma unroll 8
    for (int i = 0; i < DS * 2; i++) S += g_partials[(size_t)i * NQ + q];
    float sumw = 0.0f;
#pragma unroll 8
    for (int b = 0; b < PREP_BLOCKS; b++) sumw += g_wpart[b];

    const float LOG2PI = 1.8378770664093453f;
    out[q] = logf(S) - 0.5f * qn - 8.0f * LOG2PI - logf(sumw);
}

// ---------------------------------------------------------------------------
extern "C" void kernel_launch(void* const* d_in, const int* in_sizes, int n_in,
                              void* d_out, int out_size) {
    const float* X    = (const float*)d_in[0];  // [2048, 16]
    const float* data = (const float*)d_in[1];  // [100000, 16]
    const float* w    = (const float*)d_in[2];  // [100000]
    float* out = (float*)d_out;                 // [2048]

    kde_prep_data<<<PREP_BLOCKS, PREP_THREADS>>>(data, w);
    kde_prep_x<<<(NQ + 255) / 256, 256>>>(X);
    kde_main_kernel<<<dim3(QTILES, DS), THREADS>>>();
    kde_final_kernel<<<32, 64>>>(X, out);
}

// round 6
// speedup vs baseline: 3.0155x; 1.1351x over previous
#include <cuda_runtime.h>
#include <cuda_bf16.h>
#include <math.h>
#include <stdint.h>

#define NQ       2048
#define ND       100000
#define DIM      16
#define QTILES   16            // 2048 / 128 queries per CTA
#define DS       37            // data splits; 16*37 = 592 CTAs = 4/SM
#define TILE     256           // data points per smem tile
#define NT       11            // tiles per split
#define PTS_PER_SPLIT (TILE * NT)            // 2816
#define NPAD     (DS * PTS_PER_SPLIT)        // 104192
#define THREADS  256
#define PREP_BLOCKS  407       // NPAD / 256 exactly
#define PREP_THREADS 256

// ---- device scratch (no allocations allowed) ----
// g_dcat: per point, 16 u32 words, PERMUTED: pos 4g+{0,1,2,3} = words {g, g+4, 8+g, 12+g}
//         of the natural [dh(8 words), dl(8 words)] layout. One LDS.128 per lane
//         yields the full m16n8k16 B fragment pair for both dh and dl.
__device__ uint4 g_dcat[(size_t)NPAD * 4];
__device__ __nv_bfloat16 g_xcat[(size_t)NQ * 32];   // [yh(16), yl(16)], y = x*log2e
__device__ float g_coeff[NPAD];                     // w_j * exp(-0.5*||d||^2)
__device__ float g_partials[DS * 2 * NQ];
__device__ float g_wpart[PREP_BLOCKS];
__device__ float g_logsumw;

// ---- helpers ----
__device__ __forceinline__ uint32_t s2u(const void* p) {
    uint32_t a;
    asm("{ .reg .u64 t; cvta.to.shared.u64 t, %1; cvt.u32.u64 %0, t; }"
        : "=r"(a) : "l"(p));
    return a;
}
__device__ __forceinline__ void cpa16(uint32_t dst, const void* src) {
    asm volatile("cp.async.cg.shared.global [%0], [%1], 16;"
                 :: "r"(dst), "l"(src));
}
#define CP_COMMIT() asm volatile("cp.async.commit_group;" ::: "memory")
#define CP_WAIT0()  asm volatile("cp.async.wait_group 0;" ::: "memory")
#define CP_WAIT1()  asm volatile("cp.async.wait_group 1;" ::: "memory")

__device__ __forceinline__ float ex2f(float x) {
    float r; asm("ex2.approx.f32 %0, %1;" : "=f"(r) : "f"(x)); return r;
}
__device__ __forceinline__ void mma16816(float* d, const uint32_t* a,
                                         uint32_t b0, uint32_t b1) {
    asm volatile(
        "mma.sync.aligned.m16n8k16.row.col.f32.bf16.bf16.f32 "
        "{%0,%1,%2,%3}, {%4,%5,%6,%7}, {%8,%9}, {%0,%1,%2,%3};"
        : "+f"(d[0]), "+f"(d[1]), "+f"(d[2]), "+f"(d[3])
        : "r"(a[0]), "r"(a[1]), "r"(a[2]), "r"(a[3]), "r"(b0), "r"(b1));
}
__device__ __forceinline__ void lds128(uint32_t addr, uint32_t* v) {
    asm volatile("ld.shared.v4.u32 {%0,%1,%2,%3}, [%4];"
                 : "=r"(v[0]), "=r"(v[1]), "=r"(v[2]), "=r"(v[3]) : "r"(addr));
}

// ---------------------------------------------------------------------------
// Prep 1: one point per thread. bf16 hi/lo split, permuted word layout,
// coeff = w*exp(-||d||^2/2), block-partial sums of w.
// ---------------------------------------------------------------------------
__global__ __launch_bounds__(PREP_THREADS)
void kde_prep_data(const float* __restrict__ data,
                   const float* __restrict__ w) {
    int t = threadIdx.x;
    int j = blockIdx.x * PREP_THREADS + t;   // < NPAD always (grid exact)

    uint32_t wd[16];   // natural words: 0..7 = dh pairs, 8..15 = dl pairs
    float cj = 0.0f, wj = 0.0f;
    if (j < ND) {
        const float4* src = (const float4*)(data + (size_t)j * DIM);
        float dn = 0.0f;
#pragma unroll
        for (int v = 0; v < 4; v++) {
            float4 p = src[v];
            dn += p.x * p.x + p.y * p.y + p.z * p.z + p.w * p.w;
            float e[4] = {p.x, p.y, p.z, p.w};
#pragma unroll
            for (int u = 0; u < 2; u++) {
                float a = e[u * 2], b = e[u * 2 + 1];
                __nv_bfloat16 ha = __float2bfloat16_rn(a);
                __nv_bfloat16 hb = __float2bfloat16_rn(b);
                float la = a - __bfloat162float(ha);
                float lb = b - __bfloat162float(hb);
                uint32_t hw = ((uint32_t)*(uint16_t*)&hb << 16) | *(uint16_t*)&ha;
                __nv_bfloat16 hla = __float2bfloat16_rn(la);
                __nv_bfloat16 hlb = __float2bfloat16_rn(lb);
                uint32_t lw = ((uint32_t)*(uint16_t*)&hlb << 16) | *(uint16_t*)&hla;
                wd[v * 2 + u] = hw;
                wd[8 + v * 2 + u] = lw;
            }
        }
        wj = w[j];
        cj = wj * __expf(-0.5f * dn);
    } else {
#pragma unroll
        for (int k = 0; k < 16; k++) wd[k] = 0u;
    }
    g_coeff[j] = cj;
    // permuted store: pos 4g+{0..3} = wd[g], wd[g+4], wd[8+g], wd[12+g]
#pragma unroll
    for (int g = 0; g < 4; g++) {
        uint4 o;
        o.x = wd[g]; o.y = wd[g + 4]; o.z = wd[8 + g]; o.w = wd[12 + g];
        g_dcat[(size_t)j * 4 + g] = o;
    }

    __shared__ float red[PREP_THREADS];
    red[t] = wj;
    __syncthreads();
#pragma unroll
    for (int s = PREP_THREADS / 2; s > 0; s >>= 1) {
        if (t < s) red[t] += red[t + s];
        __syncthreads();
    }
    if (t == 0) g_wpart[blockIdx.x] = red[0];
}

// ---------------------------------------------------------------------------
// Prep 2: queries -> y = x*log2e, split bf16 -> [yh(16), yl(16)].
// Block 0 additionally reduces g_wpart -> g_logsumw (runs after prep_data).
// ---------------------------------------------------------------------------
__global__ void kde_prep_x(const float* __restrict__ X) {
    int q = blockIdx.x * blockDim.x + threadIdx.x;
    if (q < NQ) {
        const float LOG2E = 1.4426950408889634f;
        __nv_bfloat16 row[32];
        const float4* src = (const float4*)(X + (size_t)q * DIM);
#pragma unroll
        for (int v = 0; v < 4; v++) {
            float4 p = src[v];
            float e[4] = {p.x, p.y, p.z, p.w};
#pragma unroll
            for (int u = 0; u < 4; u++) {
                int k = v * 4 + u;
                float y = e[u] * LOG2E;
                __nv_bfloat16 h = __float2bfloat16_rn(y);
                __nv_bfloat16 l = __float2bfloat16_rn(y - __bfloat162float(h));
                row[k]      = h;
                row[16 + k] = l;
            }
        }
        uint4* dst = (uint4*)(g_xcat + (size_t)q * 32);
        const uint4* srcr = (const uint4*)row;
#pragma unroll
        for (int v = 0; v < 4; v++) dst[v] = srcr[v];
    }

    if (blockIdx.x == 0) {
        __shared__ float red[256];
        int t = threadIdx.x;
        float s = 0.0f;
        for (int b = t; b < PREP_BLOCKS; b += 256) s += g_wpart[b];
        red[t] = s;
        __syncthreads();
#pragma unroll
        for (int st = 128; st > 0; st >>= 1) {
            if (t < st) red[t] += red[t + st];
            __syncthreads();
        }
        if (t == 0) g_logsumw = logf(red[0]);
    }
}

// ---------------------------------------------------------------------------
// Main: CTA (qt, ds): 128 queries x 2816 points.
//   Warp w: wm = w>>1 (32 queries = 2 m-tiles), wn = w&1 (128 points).
//   Per 8-pt n-tile: 1 LDS.128 -> {dh_b0, dh_b1, dl_b0, dl_b1};
//   3 MMAs per m-tile (yh*dh, yl*dh, yh*dl), ex2 + coeff FMA epilogue.
//   Double-buffered 256-pt cp.async tiles.
// ---------------------------------------------------------------------------
__global__ __launch_bounds__(THREADS, 4)
void kde_main_kernel() {
    __shared__ uint4 sd[2][TILE * 4];   // 2 x 16 KB, 64B per point (permuted)
    __shared__ float sc[2][TILE];

    int tid = threadIdx.x;
    int w = tid >> 5, lane = tid & 31;
    int wm = w >> 1, wn = w & 1;
    int qt = blockIdx.x, ds = blockIdx.y;
    int p0base = ds * PTS_PER_SPLIT;
    int r = lane >> 2, c2 = (lane & 3) * 2;

    // A fragments: 32 queries (2 m-tiles), yh + yl
    int qb = qt * 128 + wm * 32;
    uint32_t afrag[2][2][4];
#pragma unroll
    for (int mt = 0; mt < 2; mt++)
#pragma unroll
        for (int tt = 0; tt < 2; tt++) {
            const __nv_bfloat16* base =
                g_xcat + (size_t)(qb + mt * 16 + r) * 32 + tt * 16 + c2;
            afrag[mt][tt][0] = *(const uint32_t*)(base);
            afrag[mt][tt][1] = *(const uint32_t*)(base + 8 * 32);
            afrag[mt][tt][2] = *(const uint32_t*)(base + 8);
            afrag[mt][tt][3] = *(const uint32_t*)(base + 8 * 32 + 8);
        }

    // Stage tile 0
    {
        const char* bsrc = (const char*)(g_dcat + (size_t)p0base * 4);
        uint32_t sbb = s2u(sd[0]);
#pragma unroll
        for (int i = tid; i < TILE * 4; i += THREADS)
            cpa16(sbb + i * 16, bsrc + i * 16);
        if (tid < 64)
            cpa16(s2u(sc[0]) + tid * 16, (const char*)(g_coeff + p0base) + tid * 16);
        CP_COMMIT();
    }

    float acc[2][2] = {{0.0f, 0.0f}, {0.0f, 0.0f}};
    int buf = 0;

    for (int it = 0; it < NT; ++it) {
        if (it + 1 < NT) {
            int p0 = p0base + (it + 1) * TILE;
            const char* bsrc = (const char*)(g_dcat + (size_t)p0 * 4);
            uint32_t sbb = s2u(sd[buf ^ 1]);
#pragma unroll
            for (int i = tid; i < TILE * 4; i += THREADS)
                cpa16(sbb + i * 16, bsrc + i * 16);
            if (tid < 64)
                cpa16(s2u(sc[buf ^ 1]) + tid * 16, (const char*)(g_coeff + p0) + tid * 16);
            CP_COMMIT();
            CP_WAIT1();   // tile `it` resident
        } else {
            CP_WAIT0();
        }
        __syncthreads();

        uint32_t sdb = s2u(sd[buf]);
        const float* scf = sc[buf];
#pragma unroll
        for (int nt = 0; nt < 16; nt++) {
            int n0 = wn * 128 + nt * 8;
            uint32_t b[4];
            lds128(sdb + (uint32_t)(n0 + r) * 64 + (uint32_t)(lane & 3) * 16, b);
            float d0[4] = {0, 0, 0, 0}, d1[4] = {0, 0, 0, 0};
            // b[0],b[1] = dh fragment; b[2],b[3] = dl fragment
            mma16816(d0, afrag[0][0], b[0], b[1]);   // yh * dh
            mma16816(d1, afrag[1][0], b[0], b[1]);
            mma16816(d0, afrag[0][1], b[0], b[1]);   // yl * dh
            mma16816(d1, afrag[1][1], b[0], b[1]);
            mma16816(d0, afrag[0][0], b[2], b[3]);   // yh * dl
            mma16816(d1, afrag[1][0], b[2], b[3]);

            float2 cj = *(const float2*)(scf + n0 + c2);
            acc[0][0] = fmaf(cj.x, ex2f(d0[0]), acc[0][0]);
            acc[0][0] = fmaf(cj.y, ex2f(d0[1]), acc[0][0]);
            acc[0][1] = fmaf(cj.x, ex2f(d0[2]), acc[0][1]);
            acc[0][1] = fmaf(cj.y, ex2f(d0[3]), acc[0][1]);
            acc[1][0] = fmaf(cj.x, ex2f(d1[0]), acc[1][0]);
            acc[1][0] = fmaf(cj.y, ex2f(d1[1]), acc[1][0]);
            acc[1][1] = fmaf(cj.x, ex2f(d1[2]), acc[1][1]);
            acc[1][1] = fmaf(cj.y, ex2f(d1[3]), acc[1][1]);
        }
        __syncthreads();  // done reading buf before restage
        buf ^= 1;
    }

    // Reduce over the 4 column-lanes (fixed order, deterministic)
#pragma unroll
    for (int mt = 0; mt < 2; mt++)
#pragma unroll
        for (int hh = 0; hh < 2; hh++) {
            float v = acc[mt][hh];
            v += __shfl_xor_sync(0xFFFFFFFFu, v, 1);
            v += __shfl_xor_sync(0xFFFFFFFFu, v, 2);
            acc[mt][hh] = v;
        }
    if ((lane & 3) == 0) {
        size_t base = (size_t)(ds * 2 + wn) * NQ + qb;
        g_partials[base + 0 * 16 + r]     = acc[0][0];
        g_partials[base + 0 * 16 + r + 8] = acc[0][1];
        g_partials[base + 1 * 16 + r]     = acc[1][0];
        g_partials[base + 1 * 16 + r + 8] = acc[1][1];
    }
}

// ---------------------------------------------------------------------------
// Finalize: log(S) - 0.5||x||^2 - 8*log(2*pi) - logsumw
// ---------------------------------------------------------------------------
__global__ void kde_final_kernel(const float* __restrict__ X,
                                 float* __restrict__ out) {
    int q = blockIdx.x * blockDim.x + threadIdx.x;
    if (q >= NQ) return;

    float qn = 0.0f;
    const float4* row = (const float4*)(X + (size_t)q * DIM);
#pragma unroll
    for (int v = 0; v < 4; v++) {
        float4 p = row[v];
        qn += p.x * p.x + p.y * p.y + p.z * p.z + p.w * p.w;
    }
    float S = 0.0f;
#pragma unroll 8
    for (int i = 0; i < DS * 2; i++) S += g_partials[(size_t)i * NQ + q];

    const float LOG2PI = 1.8378770664093453f;
    out[q] = logf(S) - 0.5f * qn - 8.0f * LOG2PI - g_logsumw;
}

// ---------------------------------------------------------------------------
extern "C" void kernel_launch(void* const* d_in, const int* in_sizes, int n_in,
                              void* d_out, int out_size) {
    const float* X    = (const float*)d_in[0];  // [2048, 16]
    const float* data = (const float*)d_in[1];  // [100000, 16]
    const float* w    = (const float*)d_in[2];  // [100000]
    float* out = (float*)d_out;                 // [2048]

    kde_prep_data<<<PREP_BLOCKS, PREP_THREADS>>>(data, w);
    kde_prep_x<<<(NQ + 255) / 256, 256>>>(X);
    kde_main_kernel<<<dim3(QTILES, DS), THREADS>>>();
    kde_final_kernel<<<16, 128>>>(X, out);
}

// round 7
// speedup vs baseline: 3.8223x; 1.2676x over previous
#include <cuda_runtime.h>
#include <cuda_bf16.h>
#include <math.h>
#include <stdint.h>

#define NQ       2048
#define ND       100000
#define DIM      16
#define QTILES   16            // 2048 / 128 queries per CTA
#define DS       37            // data splits; 16*37 = 592 CTAs = 4/SM
#define TILE     256           // data points per smem tile
#define NT       11            // tiles per split
#define PTS_PER_SPLIT (TILE * NT)            // 2816
#define NPAD     (DS * PTS_PER_SPLIT)        // 104192
#define THREADS  256
#define PREP_BLOCKS  407       // NPAD / 256 exactly
#define PREP_THREADS 256
#define PROW     80            // padded partials row (74 used)

// ---- device scratch (no allocations allowed) ----
// g_dcat: per point, 16 tf32 words, PERMUTED: pos 4g+{0..3} = natural words
//         {g, g+4, g+8, g+12}. One LDS.128 per lane yields both k8 B
//         fragments (b0_kc0, b1_kc0, b0_kc1, b1_kc1) for m16n8k8 tf32.
__device__ float4 g_dcat[(size_t)NPAD * 4];
__device__ float g_xcat[(size_t)NQ * 16];   // y = x*log2e, tf32-rounded
__device__ float g_coeff[NPAD];             // w_j * exp(-0.5*||d||^2)
__device__ float g_partials[(size_t)NQ * PROW];
__device__ float g_wpart[PREP_BLOCKS];

// ---- helpers ----
__device__ __forceinline__ uint32_t s2u(const void* p) {
    uint32_t a;
    asm("{ .reg .u64 t; cvta.to.shared.u64 t, %1; cvt.u32.u64 %0, t; }"
        : "=r"(a) : "l"(p));
    return a;
}
__device__ __forceinline__ void cpa16(uint32_t dst, const void* src) {
    asm volatile("cp.async.cg.shared.global [%0], [%1], 16;"
                 :: "r"(dst), "l"(src));
}
#define CP_COMMIT() asm volatile("cp.async.commit_group;" ::: "memory")
#define CP_WAIT0()  asm volatile("cp.async.wait_group 0;" ::: "memory")
#define CP_WAIT1()  asm volatile("cp.async.wait_group 1;" ::: "memory")

__device__ __forceinline__ float ex2f(float x) {
    float r; asm("ex2.approx.f32 %0, %1;" : "=f"(r) : "f"(x)); return r;
}
__device__ __forceinline__ float tf32r(float x) {
    float r; asm("cvt.rna.tf32.f32 %0, %1;" : "=f"(r) : "f"(x)); return r;
}
__device__ __forceinline__ void mma_tf32(float* d, const uint32_t* a,
                                         uint32_t b0, uint32_t b1) {
    asm volatile(
        "mma.sync.aligned.m16n8k8.row.col.f32.tf32.tf32.f32 "
        "{%0,%1,%2,%3}, {%4,%5,%6,%7}, {%8,%9}, {%0,%1,%2,%3};"
        : "+f"(d[0]), "+f"(d[1]), "+f"(d[2]), "+f"(d[3])
        : "r"(a[0]), "r"(a[1]), "r"(a[2]), "r"(a[3]), "r"(b0), "r"(b1));
}
__device__ __forceinline__ void lds128(uint32_t addr, uint32_t* v) {
    asm volatile("ld.shared.v4.u32 {%0,%1,%2,%3}, [%4];"
                 : "=r"(v[0]), "=r"(v[1]), "=r"(v[2]), "=r"(v[3]) : "r"(addr));
}

// ---------------------------------------------------------------------------
// Prep (merged): point j -> tf32 permuted layout + coeff; query j (j<NQ) ->
// y = x*log2e tf32; block-partial sums of w.
// ---------------------------------------------------------------------------
__global__ __launch_bounds__(PREP_THREADS)
void kde_prep_kernel(const float* __restrict__ data,
                     const float* __restrict__ w,
                     const float* __restrict__ X) {
    int t = threadIdx.x;
    int j = blockIdx.x * PREP_THREADS + t;   // < NPAD (grid exact)

    float wd[16];
    float cj = 0.0f, wj = 0.0f;
    if (j < ND) {
        const float4* src = (const float4*)(data + (size_t)j * DIM);
        float dn = 0.0f;
#pragma unroll
        for (int v = 0; v < 4; v++) {
            float4 p = src[v];
            dn += p.x * p.x + p.y * p.y + p.z * p.z + p.w * p.w;
            wd[v * 4 + 0] = tf32r(p.x);
            wd[v * 4 + 1] = tf32r(p.y);
            wd[v * 4 + 2] = tf32r(p.z);
            wd[v * 4 + 3] = tf32r(p.w);
        }
        wj = w[j];
        cj = wj * __expf(-0.5f * dn);
    } else {
#pragma unroll
        for (int k = 0; k < 16; k++) wd[k] = 0.0f;
    }
    g_coeff[j] = cj;
    // permuted store: pos 4g+{0..3} = wd[g], wd[g+4], wd[g+8], wd[g+12]
#pragma unroll
    for (int g = 0; g < 4; g++) {
        float4 o;
        o.x = wd[g]; o.y = wd[g + 4]; o.z = wd[g + 8]; o.w = wd[g + 12];
        g_dcat[(size_t)j * 4 + g] = o;
    }

    if (j < NQ) {
        const float LOG2E = 1.4426950408889634f;
        const float4* src = (const float4*)(X + (size_t)j * DIM);
        float4* dst = (float4*)(g_xcat + (size_t)j * 16);
#pragma unroll
        for (int v = 0; v < 4; v++) {
            float4 p = src[v];
            float4 o;
            o.x = tf32r(p.x * LOG2E);
            o.y = tf32r(p.y * LOG2E);
            o.z = tf32r(p.z * LOG2E);
            o.w = tf32r(p.w * LOG2E);
            dst[v] = o;
        }
    }

    __shared__ float red[PREP_THREADS];
    red[t] = wj;
    __syncthreads();
#pragma unroll
    for (int s = PREP_THREADS / 2; s > 0; s >>= 1) {
        if (t < s) red[t] += red[t + s];
        __syncthreads();
    }
    if (t == 0) g_wpart[blockIdx.x] = red[0];
}

// ---------------------------------------------------------------------------
// Main: CTA (qt, ds): 128 queries x 2816 points, tf32 m16n8k8.
//   Warp w: wm = w>>1 (32 queries = 2 m-tiles), wn = w&1 (128 points).
//   Per 8-pt n-tile: 1 LDS.128 -> both k8 B fragments; 2 MMAs per m-tile.
// ---------------------------------------------------------------------------
__global__ __launch_bounds__(THREADS, 4)
void kde_main_kernel() {
    __shared__ uint4 sd[2][TILE * 4];   // 2 x 16 KB, 64B per point (permuted)
    __shared__ float sc[2][TILE];

    int tid = threadIdx.x;
    int w = tid >> 5, lane = tid & 31;
    int wm = w >> 1, wn = w & 1;
    int qt = blockIdx.x, ds = blockIdx.y;
    int p0base = ds * PTS_PER_SPLIT;
    int r = lane >> 2, cg = lane & 3, c2 = cg * 2;

    // A fragments: 32 queries (2 m-tiles) x 2 k-chunks, tf32
    int qb = qt * 128 + wm * 32;
    uint32_t afrag[2][2][4];
#pragma unroll
    for (int mt = 0; mt < 2; mt++)
#pragma unroll
        for (int kc = 0; kc < 2; kc++) {
            const uint32_t* base =
                (const uint32_t*)g_xcat + (size_t)(qb + mt * 16 + r) * 16 + kc * 8 + cg;
            afrag[mt][kc][0] = base[0];
            afrag[mt][kc][1] = base[8 * 16];
            afrag[mt][kc][2] = base[4];
            afrag[mt][kc][3] = base[8 * 16 + 4];
        }

    // Stage tile 0
    {
        const char* bsrc = (const char*)(g_dcat + (size_t)p0base * 4);
        uint32_t sbb = s2u(sd[0]);
#pragma unroll
        for (int i = tid; i < TILE * 4; i += THREADS)
            cpa16(sbb + i * 16, bsrc + i * 16);
        if (tid < 64)
            cpa16(s2u(sc[0]) + tid * 16, (const char*)(g_coeff + p0base) + tid * 16);
        CP_COMMIT();
    }

    float acc[2][2] = {{0.0f, 0.0f}, {0.0f, 0.0f}};
    int buf = 0;

    for (int it = 0; it < NT; ++it) {
        if (it + 1 < NT) {
            int p0 = p0base + (it + 1) * TILE;
            const char* bsrc = (const char*)(g_dcat + (size_t)p0 * 4);
            uint32_t sbb = s2u(sd[buf ^ 1]);
#pragma unroll
            for (int i = tid; i < TILE * 4; i += THREADS)
                cpa16(sbb + i * 16, bsrc + i * 16);
            if (tid < 64)
                cpa16(s2u(sc[buf ^ 1]) + tid * 16, (const char*)(g_coeff + p0) + tid * 16);
            CP_COMMIT();
            CP_WAIT1();   // tile `it` resident
        } else {
            CP_WAIT0();
        }
        __syncthreads();

        uint32_t sdb = s2u(sd[buf]);
        const float* scf = sc[buf];
#pragma unroll
        for (int nt = 0; nt < 16; nt++) {
            int n0 = wn * 128 + nt * 8;
            uint32_t b[4];
            lds128(sdb + (uint32_t)(n0 + r) * 64 + (uint32_t)cg * 16, b);
            float d0[4] = {0, 0, 0, 0}, d1[4] = {0, 0, 0, 0};
            // b[0],b[1] = k-chunk 0 fragment; b[2],b[3] = k-chunk 1
            mma_tf32(d0, afrag[0][0], b[0], b[1]);
            mma_tf32(d1, afrag[1][0], b[0], b[1]);
            mma_tf32(d0, afrag[0][1], b[2], b[3]);
            mma_tf32(d1, afrag[1][1], b[2], b[3]);

            float2 cj = *(const float2*)(scf + n0 + c2);
            acc[0][0] = fmaf(cj.x, ex2f(d0[0]), acc[0][0]);
            acc[0][0] = fmaf(cj.y, ex2f(d0[1]), acc[0][0]);
            acc[0][1] = fmaf(cj.x, ex2f(d0[2]), acc[0][1]);
            acc[0][1] = fmaf(cj.y, ex2f(d0[3]), acc[0][1]);
            acc[1][0] = fmaf(cj.x, ex2f(d1[0]), acc[1][0]);
            acc[1][0] = fmaf(cj.y, ex2f(d1[1]), acc[1][0]);
            acc[1][1] = fmaf(cj.x, ex2f(d1[2]), acc[1][1]);
            acc[1][1] = fmaf(cj.y, ex2f(d1[3]), acc[1][1]);
        }
        __syncthreads();  // done reading buf before restage
        buf ^= 1;
    }

    // Reduce over the 4 column-lanes (fixed order, deterministic)
#pragma unroll
    for (int mt = 0; mt < 2; mt++)
#pragma unroll
        for (int hh = 0; hh < 2; hh++) {
            float v = acc[mt][hh];
            v += __shfl_xor_sync(0xFFFFFFFFu, v, 1);
            v += __shfl_xor_sync(0xFFFFFFFFu, v, 2);
            acc[mt][hh] = v;
        }
    if (cg == 0) {
        int col = ds * 2 + wn;
        g_partials[(size_t)(qb + r) * PROW + col]          = acc[0][0];
        g_partials[(size_t)(qb + r + 8) * PROW + col]      = acc[0][1];
        g_partials[(size_t)(qb + 16 + r) * PROW + col]     = acc[1][0];
        g_partials[(size_t)(qb + 16 + r + 8) * PROW + col] = acc[1][1];
    }
}

// ---------------------------------------------------------------------------
// Finalize: warp per query. Each block also reduces g_wpart -> logsumw.
//   log_density = log(S) - 0.5||x||^2 - 8*log(2*pi) - logsumw
// ---------------------------------------------------------------------------
__global__ __launch_bounds__(256)
void kde_final_kernel(const float* __restrict__ X,
                      float* __restrict__ out) {
    __shared__ float red[256];
    __shared__ float s_logsumw;
    int t = threadIdx.x;
    int w = t >> 5, lane = t & 31;

    float s = g_wpart[t];                       // 256 <= PREP_BLOCKS
    if (t + 256 < PREP_BLOCKS) s += g_wpart[t + 256];
    red[t] = s;
    __syncthreads();
#pragma unroll
    for (int st = 128; st > 0; st >>= 1) {
        if (t < st) red[t] += red[t + st];
        __syncthreads();
    }
    if (t == 0) s_logsumw = logf(red[0]);
    __syncthreads();

    int q = blockIdx.x * 8 + w;
    const float* pr = g_partials + (size_t)q * PROW;
    float S = pr[lane] + pr[lane + 32];
    if (lane < DS * 2 - 64) S += pr[lane + 64];
    // fixed-order shfl reduction
    S += __shfl_xor_sync(0xFFFFFFFFu, S, 16);
    S += __shfl_xor_sync(0xFFFFFFFFu, S, 8);
    S += __shfl_xor_sync(0xFFFFFFFFu, S, 4);
    S += __shfl_xor_sync(0xFFFFFFFFu, S, 2);
    S += __shfl_xor_sync(0xFFFFFFFFu, S, 1);

    if (lane == 0) {
        float qn = 0.0f;
        const float4* row = (const float4*)(X + (size_t)q * DIM);
#pragma unroll
        for (int v = 0; v < 4; v++) {
            float4 p = row[v];
            qn += p.x * p.x + p.y * p.y + p.z * p.z + p.w * p.w;
        }
        const float LOG2PI = 1.8378770664093453f;
        out[q] = logf(S) - 0.5f * qn - 8.0f * LOG2PI - s_logsumw;
    }
}

// ---------------------------------------------------------------------------
extern "C" void kernel_launch(void* const* d_in, const int* in_sizes, int n_in,
                              void* d_out, int out_size) {
    const float* X    = (const float*)d_in[0];  // [2048, 16]
    const float* data = (const float*)d_in[1];  // [100000, 16]
    const float* w    = (const float*)d_in[2];  // [100000]
    float* out = (float*)d_out;                 // [2048]

    kde_prep_kernel<<<PREP_BLOCKS, PREP_THREADS>>>(data, w, X);
    kde_main_kernel<<<dim3(QTILES, DS), THREADS>>>();
    kde_final_kernel<<<NQ / 8, 256>>>(X, out);
}